// round 15
// baseline (speedup 1.0000x reference)
#include <cuda_runtime.h>
#include <cuda_fp16.h>
#include <math.h>
#include <stdint.h>

#define Bn 512
#define Tn 256
#define Cn 192
#define Hn 64

// Scratch (device globals = sanctioned alloc-free mechanism). Packed half2 words.
__device__ unsigned g_q[(size_t)Bn * Tn * 32];   // [b*t][32w] = [t][64h] half, pre-scaled
__device__ unsigned g_k[(size_t)Bn * Tn * 32];   // [b][t][64h] half
__device__ unsigned g_vT[(size_t)Bn * 64 * 128]; // [b][64h][256t] half
__device__ float g_pos[Tn * 128];                // [t][ pos_k | pos_q ]  fp32
__device__ float g_bias[Tn * Tn];                // fp32 exact

// ---------------------------------------------------------------------------
// fp16 m16n8k16: A = 4 packed-half2 regs, B = 2, C/D fp32 x4
__device__ __forceinline__ void mma_f16(float c[4], const unsigned a[4],
                                        unsigned b0, unsigned b1) {
    asm volatile(
        "mma.sync.aligned.m16n8k16.row.col.f32.f16.f16.f32 "
        "{%0,%1,%2,%3}, {%4,%5,%6,%7}, {%8,%9}, {%0,%1,%2,%3};"
        : "+f"(c[0]), "+f"(c[1]), "+f"(c[2]), "+f"(c[3])
        : "r"(a[0]), "r"(a[1]), "r"(a[2]), "r"(a[3]), "r"(b0), "r"(b1));
}

// pack two fp32 -> half2 word, lo half = first arg
__device__ __forceinline__ unsigned packh2(float lo, float hi) {
    unsigned p;
    asm("cvt.rn.f16x2.f32 %0, %1, %2;" : "=r"(p) : "f"(hi), "f"(lo));
    return p;
}

__device__ __forceinline__ unsigned smaddr(const void* p) {
    return (unsigned)__cvta_generic_to_shared(p);
}
#define CP_ASYNC16(dst, src) \
    asm volatile("cp.async.ca.shared.global [%0], [%1], 16;" :: "r"(dst), "l"(src))
#define CP_COMMIT() asm volatile("cp.async.commit_group;")

// ---------------------------------------------------------------------------
// Kernel 1: FUSED QKV, 512 threads (spill-free: acc[3][4][4] = 48 regs/thread).
// grid 1024 (128-row tiles). Warp (16 total) = 16 rows x 32 cols x 3 sels:
// wr = w>>1 rows wr*16, wc = w&1 cols wc*32. x staged ONCE per tile (fp32,
// [128][40], double-buffered cp.async, A-frags shared across sels). W staged
// fragment-native as TWO half2 planes (b0 @slot, b1 @slot+9216), slot =
// ((sel*12+kstep)*8+nt)*32 + 8tg+gq -> LDS.32 banks all-distinct (audited).
// smem 114.7KB -> 1 CTA/SM (16 warps). Outputs identical to round-12 qkv.
// ---------------------------------------------------------------------------
#define XST 40
__global__ __launch_bounds__(512, 1) void qkv_fused_kernel(const float* __restrict__ x,
                                                           const float* __restrict__ Wq,
                                                           const float* __restrict__ Wk,
                                                           const float* __restrict__ Wv) {
    extern __shared__ unsigned smw[];
    unsigned* W_sh = smw;                                   // 18432 words (2 planes)
    float* bufs[2] = { (float*)(smw + 18432),
                       (float*)(smw + 18432) + 5120 };      // 128*40 each

    const int by = blockIdx.x;
    const int tid = threadIdx.x;
    const float* __restrict__ xc = x + (size_t)by * 128 * 192;

    // prologue: x chunk 0 (k 0..31): 128 rows x 8 x 16B = 1024 cp.async
    for (int f = tid; f < 1024; f += 512) {
        int r = f >> 3, c4 = f & 7;
        CP_ASYNC16(smaddr(bufs[0] + r * XST + c4 * 4), xc + r * 192 + c4 * 4);
    }
    CP_COMMIT();

    // stage W fragment-native: slot -> (sel, kstep, nt, 8tg+gq)
    for (int idx = tid; idx < 9216; idx += 512) {
        int sl = idx / 3072;
        int r = idx - sl * 3072;
        int kstep = r >> 8;
        int r2 = r & 255;
        int nt = r2 >> 5;
        int slot = r2 & 31;
        int tg2 = slot >> 3, gq2 = slot & 7;
        const float* __restrict__ W = (sl == 0) ? Wq : ((sl == 1) ? Wk : Wv);
        int n = nt * 8 + gq2;
        int k0 = kstep * 16 + 2 * tg2;
        W_sh[idx]        = packh2(W[k0 * 64 + n],       W[(k0 + 1) * 64 + n]);
        W_sh[9216 + idx] = packh2(W[(k0 + 8) * 64 + n], W[(k0 + 9) * 64 + n]);
    }

    const int w = tid >> 5, lane = tid & 31;
    const int wr = w >> 1, wc = w & 1;
    const int gq = lane >> 2, tg = lane & 3;

    float acc[3][4][4];
#pragma unroll
    for (int sl = 0; sl < 3; sl++)
#pragma unroll
        for (int n = 0; n < 4; n++)
#pragma unroll
            for (int i = 0; i < 4; i++) acc[sl][n][i] = 0.0f;

    int buf = 0;
    for (int c = 0; c < 6; c++) {
        if (c < 5) {
            const float* src = xc + (c + 1) * 32;
            float* dst = bufs[buf ^ 1];
            for (int f = tid; f < 1024; f += 512) {
                int r = f >> 3, c4 = f & 7;
                CP_ASYNC16(smaddr(dst + r * XST + c4 * 4), src + r * 192 + c4 * 4);
            }
            CP_COMMIT();
            asm volatile("cp.async.wait_group 1;");
        } else {
            asm volatile("cp.async.wait_group 0;");
        }
        __syncthreads();

        const float* xs = bufs[buf] + (wr * 16) * XST;
#pragma unroll
        for (int ks2 = 0; ks2 < 2; ks2++) {
            const int kb = ks2 * 16 + 2 * tg;
            unsigned a0[4];
            {
                float2 v;
                v = *(const float2*)(xs + gq * XST + kb);           a0[0] = packh2(v.x, v.y);
                v = *(const float2*)(xs + (gq + 8) * XST + kb);     a0[1] = packh2(v.x, v.y);
                v = *(const float2*)(xs + gq * XST + kb + 8);       a0[2] = packh2(v.x, v.y);
                v = *(const float2*)(xs + (gq + 8) * XST + kb + 8); a0[3] = packh2(v.x, v.y);
            }
            const int kstep = c * 2 + ks2;
#pragma unroll
            for (int sl = 0; sl < 3; sl++) {
                const unsigned* wp =
                    W_sh + ((sl * 12 + kstep) * 8 + wc * 4) * 32 + 8 * tg + gq;
#pragma unroll
                for (int nt = 0; nt < 4; nt++) {
                    unsigned b0 = wp[nt * 32];
                    unsigned b1 = wp[9216 + nt * 32];
                    mma_f16(acc[sl][nt], a0, b0, b1);
                }
            }
        }
        __syncthreads();
        buf ^= 1;
    }

    // Epilogues. b = by>>1; rows tt = (by&1)*128 + wr*16 + gq (and +8).
    const int b = by >> 1;
    const int tt = (by & 1) * 128 + wr * 16 + gq;
    {
        const float qs = rsqrtf(192.0f);
        unsigned* qo = g_q + (size_t)b * 256 * 32;
#pragma unroll
        for (int nt = 0; nt < 4; nt++) {
            int wi = (wc * 4 + nt) * 4 + tg;
            qo[tt * 32 + wi]       = packh2(acc[0][nt][0] * qs, acc[0][nt][1] * qs);
            qo[(tt + 8) * 32 + wi] = packh2(acc[0][nt][2] * qs, acc[0][nt][3] * qs);
        }
    }
    {
        unsigned* ko = g_k + (size_t)b * 256 * 32;
#pragma unroll
        for (int nt = 0; nt < 4; nt++) {
            int wi = (wc * 4 + nt) * 4 + tg;
            ko[tt * 32 + wi]       = packh2(acc[1][nt][0], acc[1][nt][1]);
            ko[(tt + 8) * 32 + wi] = packh2(acc[1][nt][2], acc[1][nt][3]);
        }
    }
    {
        // v -> [h][t]: adjacent t in lanes gq, gq^1 (lane^4); even-gq packs.
        unsigned* vo = g_vT + (size_t)b * 8192;
        const bool even = ((gq & 1) == 0);
#pragma unroll
        for (int nt = 0; nt < 4; nt++) {
            int cc = (wc * 4 + nt) * 8 + 2 * tg;
            float a0v = acc[2][nt][0], a1v = acc[2][nt][1];
            float a2v = acc[2][nt][2], a3v = acc[2][nt][3];
            float p0 = __shfl_xor_sync(0xffffffffu, a0v, 4);
            float p1 = __shfl_xor_sync(0xffffffffu, a1v, 4);
            float p2 = __shfl_xor_sync(0xffffffffu, a2v, 4);
            float p3 = __shfl_xor_sync(0xffffffffu, a3v, 4);
            if (even) {
                vo[cc * 128 + (tt >> 1)]             = packh2(a0v, p0);
                vo[(cc + 1) * 128 + (tt >> 1)]       = packh2(a1v, p1);
                vo[cc * 128 + ((tt + 8) >> 1)]       = packh2(a2v, p2);
                vo[(cc + 1) * 128 + ((tt + 8) >> 1)] = packh2(a3v, p3);
            }
        }
    }
}

// ---------------------------------------------------------------------------
// Kernel 2 + 3: positional projections and bias (tiny, fp32 exact)
// ---------------------------------------------------------------------------
__global__ __launch_bounds__(256) void pos_kernel(const float* __restrict__ pe,
                                                  const float* __restrict__ Wk,
                                                  const float* __restrict__ Wq) {
    int idx = blockIdx.x * 256 + threadIdx.x;
    int t = idx >> 7;
    int j = idx & 127;
    const float* __restrict__ W = (j < 64) ? Wk : Wq;
    int col = j & 63;
    float s = 0.0f;
#pragma unroll 4
    for (int c = 0; c < 192; c++) s = fmaf(pe[t * 192 + c], W[c * 64 + col], s);
    g_pos[idx] = s;
}

__global__ __launch_bounds__(256) void bias_kernel() {
    int i = blockIdx.x;
    int j = threadIdx.x;
    float s = 0.0f;
#pragma unroll 4
    for (int h = 0; h < 64; h++)
        s = fmaf(g_pos[i * 128 + h], g_pos[j * 128 + 64 + h], s);
    g_bias[i * 256 + j] = s;
}

// ---------------------------------------------------------------------------
// Kernel 4: flash-block attention (round-14 version; exp done IN PLACE in s
// to free the e[4][4] registers at the 128-reg cap; values identical).
// ---------------------------------------------------------------------------
#define KSW 36
#define VSW 20
__global__ __launch_bounds__(256, 2) void attn_f16_kernel(float* __restrict__ out) {
    extern __shared__ unsigned smw[];
    unsigned* kbuf[2] = { smw, smw + 1152 };          // 32*36 words each
    unsigned* vbuf[2] = { smw + 2304, smw + 3584 };   // 64*20 words each

    const int qb = blockIdx.x;
    const int b  = blockIdx.y;
    const int tid = threadIdx.x, w = tid >> 5, lane = tid & 31;
    const int gq = lane >> 2, tg = lane & 3;
    const int nj = (qb + 1) * 4;

    const unsigned* __restrict__ kg = g_k + (size_t)b * 8192;    // [t][32w]
    const unsigned* __restrict__ vg = g_vT + (size_t)b * 8192;   // [h][128w]

    const int rowg = qb * 128 + gq * 8 + w;
    const int row2 = rowg + 64;

    // Q fragments (packed half2): 16 x 32-bit loads
    unsigned qa[4][4];
    {
        const unsigned* __restrict__ qh = g_q + ((size_t)b * 256 + qb * 128) * 32;
        const int r0 = gq * 8 + w, r1 = r0 + 64;
#pragma unroll
        for (int kk = 0; kk < 4; kk++) {
            qa[kk][0] = qh[r0 * 32 + kk * 8 + tg];
            qa[kk][1] = qh[r1 * 32 + kk * 8 + tg];
            qa[kk][2] = qh[r0 * 32 + kk * 8 + tg + 4];
            qa[kk][3] = qh[r1 * 32 + kk * 8 + tg + 4];
        }
    }

    float o[8][4];
#pragma unroll
    for (int n = 0; n < 8; n++)
#pragma unroll
        for (int i = 0; i < 4; i++) o[n][i] = 0.0f;
    float m0 = -1e30f, m1 = -1e30f, l0 = 0.0f, l1 = 0.0f;

    // Prologue: stage tile 0. K: 32 rows x 8 chunks; V: 64 rows x 4 chunks.
    for (int f = tid; f < 512; f += 256) {
        if (f < 256) {
            int r = f >> 3, c8 = f & 7;
            CP_ASYNC16(smaddr(kbuf[0] + r * KSW + c8 * 4), kg + r * 32 + c8 * 4);
        } else {
            int g = f - 256;
            int h = g >> 2, c4 = g & 3;
            CP_ASYNC16(smaddr(vbuf[0] + h * VSW + c4 * 4), vg + h * 128 + c4 * 4);
        }
    }
    CP_COMMIT();

    int buf = 0;
    for (int jt = 0; jt < nj; jt++) {
        const int j0 = jt * 32;
        asm volatile("cp.async.wait_group 0;");
        __syncthreads();

        if (jt + 1 < nj) {
            const int jn = j0 + 32;
            unsigned* kn = kbuf[buf ^ 1];
            unsigned* vn = vbuf[buf ^ 1];
            for (int f = tid; f < 512; f += 256) {
                if (f < 256) {
                    int r = f >> 3, c8 = f & 7;
                    CP_ASYNC16(smaddr(kn + r * KSW + c8 * 4),
                               kg + (jn + r) * 32 + c8 * 4);
                } else {
                    int g = f - 256;
                    int h = g >> 2, c4 = g & 3;
                    CP_ASYNC16(smaddr(vn + h * VSW + c4 * 4),
                               vg + h * 128 + (jn >> 1) + c4 * 4);
                }
            }
            CP_COMMIT();
        }

        const unsigned* kb = kbuf[buf];
        const unsigned* vb = vbuf[buf];

        // Hoisted bias loads (independent of the mma chain below)
        float2 bv0[4], bv1[4];
        {
            const float* __restrict__ br0 = g_bias + (size_t)rowg * 256 + j0;
            const float* __restrict__ br1 = g_bias + (size_t)row2 * 256 + j0;
#pragma unroll
            for (int nt = 0; nt < 4; nt++) {
                int c = nt * 8 + 2 * tg;
                bv0[nt] = *(const float2*)(br0 + c);
                bv1[nt] = *(const float2*)(br1 + c);
            }
        }

        // S = Q K^T  (q pre-scaled): 16 mmas
        float s[4][4];
#pragma unroll
        for (int n = 0; n < 4; n++)
#pragma unroll
            for (int i = 0; i < 4; i++) s[n][i] = 0.0f;
#pragma unroll
        for (int kk = 0; kk < 4; kk++) {
#pragma unroll
            for (int nt = 0; nt < 4; nt++) {
                const unsigned* kb2 = kb + (nt * 8 + gq) * KSW + kk * 8 + tg;
                mma_f16(s[nt], qa[kk], kb2[0], kb2[4]);
            }
        }

        // + bias, causal mask
#pragma unroll
        for (int nt = 0; nt < 4; nt++) {
            int c = nt * 8 + 2 * tg;
            int col = j0 + c;
            s[nt][0] = (col     <= rowg) ? (s[nt][0] + bv0[nt].x) : -1e30f;
            s[nt][1] = (col + 1 <= rowg) ? (s[nt][1] + bv0[nt].y) : -1e30f;
            s[nt][2] = (col     <= row2) ? (s[nt][2] + bv1[nt].x) : -1e30f;
            s[nt][3] = (col + 1 <= row2) ? (s[nt][3] + bv1[nt].y) : -1e30f;
        }

        // online softmax
        float mx0 = -1e30f, mx1 = -1e30f;
#pragma unroll
        for (int nt = 0; nt < 4; nt++) {
            mx0 = fmaxf(mx0, fmaxf(s[nt][0], s[nt][1]));
            mx1 = fmaxf(mx1, fmaxf(s[nt][2], s[nt][3]));
        }
        mx0 = fmaxf(mx0, __shfl_xor_sync(0xffffffffu, mx0, 1));
        mx0 = fmaxf(mx0, __shfl_xor_sync(0xffffffffu, mx0, 2));
        mx1 = fmaxf(mx1, __shfl_xor_sync(0xffffffffu, mx1, 1));
        mx1 = fmaxf(mx1, __shfl_xor_sync(0xffffffffu, mx1, 2));
        float mn0 = fmaxf(m0, mx0), mn1 = fmaxf(m1, mx1);
        float al0 = __expf(m0 - mn0), al1 = __expf(m1 - mn1);
        m0 = mn0; m1 = mn1;

        // exp IN PLACE in s (frees the former e[] registers)
        float sum0 = 0.0f, sum1 = 0.0f;
#pragma unroll
        for (int nt = 0; nt < 4; nt++) {
            s[nt][0] = __expf(s[nt][0] - mn0);
            s[nt][1] = __expf(s[nt][1] - mn0);
            s[nt][2] = __expf(s[nt][2] - mn1);
            s[nt][3] = __expf(s[nt][3] - mn1);
            sum0 += s[nt][0] + s[nt][1];
            sum1 += s[nt][2] + s[nt][3];
        }
        sum0 += __shfl_xor_sync(0xffffffffu, sum0, 1);
        sum0 += __shfl_xor_sync(0xffffffffu, sum0, 2);
        sum1 += __shfl_xor_sync(0xffffffffu, sum1, 1);
        sum1 += __shfl_xor_sync(0xffffffffu, sum1, 2);
        l0 = l0 * al0 + sum0;
        l1 = l1 * al1 + sum1;

#pragma unroll
        for (int nt = 0; nt < 8; nt++) {
            o[nt][0] *= al0; o[nt][1] *= al0;
            o[nt][2] *= al1; o[nt][3] *= al1;
        }

        // O += P V : P A-frags packed directly from s registers (C-frag == A-frag)
#pragma unroll
        for (int ks = 0; ks < 2; ks++) {
            unsigned pa[4];
            pa[0] = packh2(s[2 * ks][0],     s[2 * ks][1]);
            pa[1] = packh2(s[2 * ks][2],     s[2 * ks][3]);
            pa[2] = packh2(s[2 * ks + 1][0], s[2 * ks + 1][1]);
            pa[3] = packh2(s[2 * ks + 1][2], s[2 * ks + 1][3]);
#pragma unroll
            for (int nt = 0; nt < 8; nt++) {
                const unsigned* vb2 = vb + (nt * 8 + gq) * VSW + ks * 8 + tg;
                mma_f16(o[nt], pa, vb2[0], vb2[4]);
            }
        }
        // no bottom __syncthreads — next iteration's top barrier orders restaging
        buf ^= 1;
    }

    float inv0 = 1.0f / l0, inv1 = 1.0f / l1;
    float* ob = out + ((size_t)b * 256) * 64;
#pragma unroll
    for (int nt = 0; nt < 8; nt++) {
        int c = nt * 8 + 2 * tg;
        *(float2*)(ob + (size_t)rowg * 64 + c) =
            make_float2(o[nt][0] * inv0, o[nt][1] * inv0);
        *(float2*)(ob + (size_t)row2 * 64 + c) =
            make_float2(o[nt][2] * inv1, o[nt][3] * inv1);
    }
}

// ---------------------------------------------------------------------------
extern "C" void kernel_launch(void* const* d_in, const int* in_sizes, int n_in,
                              void* d_out, int out_size) {
    const float* x  = (const float*)d_in[0];
    const float* Wk = (const float*)d_in[1];
    const float* Wq = (const float*)d_in[2];
    const float* Wv = (const float*)d_in[3];
    const float* pe = (const float*)d_in[4];
    float* out = (float*)d_out;
    (void)in_sizes; (void)n_in; (void)out_size;

    static bool attr_set = false;
    if (!attr_set) {
        cudaFuncSetAttribute(qkv_fused_kernel,
                             cudaFuncAttributeMaxDynamicSharedMemorySize, 114688);
        cudaFuncSetAttribute(attn_f16_kernel,
                             cudaFuncAttributeMaxDynamicSharedMemorySize, 19456);
        attr_set = true;
    }

    qkv_fused_kernel<<<1024, 512, 114688>>>(x, Wq, Wk, Wv);
    pos_kernel<<<128, 256>>>(pe, Wk, Wq);
    bias_kernel<<<256, 256>>>();
    attn_f16_kernel<<<dim3(2, 512), 256, 19456>>>(out);
}

// round 16
// speedup vs baseline: 1.0604x; 1.0604x over previous
#include <cuda_runtime.h>
#include <cuda_fp16.h>
#include <math.h>
#include <stdint.h>

#define Bn 512
#define Tn 256
#define Cn 192
#define Hn 64

// Scratch (device globals = sanctioned alloc-free mechanism). Packed half2 words.
// g_k / g_vT store words in FRAGMENT-PAIR PERMUTED order (see kperm/vperm).
__device__ unsigned g_q[(size_t)Bn * Tn * 32];   // [b*t][32w] = [t][64h] half, pre-scaled
__device__ unsigned g_k[(size_t)Bn * Tn * 32];   // [b][t][32w permuted]
__device__ unsigned g_vT[(size_t)Bn * 64 * 128]; // [b][64h][128w t-pairs, tile-permuted]
__device__ float g_pos[Tn * 128];                // [t][ pos_k | pos_q ]  fp32
__device__ float g_bias[Tn * Tn];                // fp32 exact

// Pair permutation: word h2 (0..31) -> position so that (h2, h2+4) of each
// 8-group land adjacent (one LDS.64 per mma B-pair).
__device__ __forceinline__ int kperm(int h2) {
    return (h2 >> 3) * 8 + (h2 & 3) * 2 + ((h2 & 4) >> 2);
}
// V: same permutation applied within each 16-word tile group.
__device__ __forceinline__ int vperm(int g) {
    int ti = g >> 4, r = g & 15;
    return ti * 16 + (r >> 3) * 8 + (r & 3) * 2 + ((r & 4) >> 2);
}

// ---------------------------------------------------------------------------
// fp16 m16n8k16: A = 4 packed-half2 regs, B = 2, C/D fp32 x4
__device__ __forceinline__ void mma_f16(float c[4], const unsigned a[4],
                                        unsigned b0, unsigned b1) {
    asm volatile(
        "mma.sync.aligned.m16n8k16.row.col.f32.f16.f16.f32 "
        "{%0,%1,%2,%3}, {%4,%5,%6,%7}, {%8,%9}, {%0,%1,%2,%3};"
        : "+f"(c[0]), "+f"(c[1]), "+f"(c[2]), "+f"(c[3])
        : "r"(a[0]), "r"(a[1]), "r"(a[2]), "r"(a[3]), "r"(b0), "r"(b1));
}

// pack two fp32 -> half2 word, lo half = first arg
__device__ __forceinline__ unsigned packh2(float lo, float hi) {
    unsigned p;
    asm("cvt.rn.f16x2.f32 %0, %1, %2;" : "=r"(p) : "f"(hi), "f"(lo));
    return p;
}

__device__ __forceinline__ unsigned smaddr(const void* p) {
    return (unsigned)__cvta_generic_to_shared(p);
}
#define CP_ASYNC16(dst, src) \
    asm volatile("cp.async.ca.shared.global [%0], [%1], 16;" :: "r"(dst), "l"(src))
#define CP_COMMIT() asm volatile("cp.async.commit_group;")

// ---------------------------------------------------------------------------
// Kernel 1: QKV projection, fp16 m16n8k16 (round-12/14 structure; bottom
// __syncthreads removed — next iteration's top barrier orders restaging).
// grid (3, 512): x = sel, y = b. 8 warps x (32 rows x 64 cols), k=192 in 6
// chunks of 32. W packed half2 [96 k2][72w]; x cp.async fp32 [256][40]
// double-buffered. 109.6KB smem -> 2 CTAs/SM. k/vT outputs pair-permuted.
// ---------------------------------------------------------------------------
#define WST 72
#define XST 40
__global__ __launch_bounds__(256, 2) void qkv_f16_kernel(const float* __restrict__ x,
                                                         const float* __restrict__ Wq,
                                                         const float* __restrict__ Wk,
                                                         const float* __restrict__ Wv) {
    extern __shared__ float sm[];
    unsigned* W_sh = (unsigned*)sm;                        // 96*72 words
    float* bufs[2] = { sm + 6912, sm + 6912 + 10240 };     // 256*40 each

    const int sel = blockIdx.x;
    const int b = blockIdx.y;
    const int tid = threadIdx.x;
    const float* __restrict__ W = (sel == 0) ? Wq : ((sel == 1) ? Wk : Wv);
    const float* __restrict__ xc = x + (size_t)b * 256 * 192;

    // prologue: chunk 0 (k 0..31)
    for (int f = tid; f < 2048; f += 256) {
        int r = f >> 3, c4 = f & 7;
        CP_ASYNC16(smaddr(bufs[0] + r * XST + c4 * 4), xc + r * 192 + c4 * 4);
    }
    CP_COMMIT();

    // stage W packed half2: word (k2, n) = (W[2k2][n], W[2k2+1][n])
    for (int idx = tid; idx < 6144; idx += 256) {
        int k2 = idx >> 6, n = idx & 63;
        W_sh[k2 * WST + n] = packh2(W[(2 * k2) * 64 + n], W[(2 * k2 + 1) * 64 + n]);
    }

    const int w = tid >> 5, lane = tid & 31;
    const int gq = lane >> 2, tg = lane & 3;

    float acc[2][8][4];
#pragma unroll
    for (int r = 0; r < 2; r++)
#pragma unroll
        for (int n = 0; n < 8; n++)
#pragma unroll
            for (int i = 0; i < 4; i++) acc[r][n][i] = 0.0f;

    int buf = 0;
    for (int c = 0; c < 6; c++) {
        if (c < 5) { asm volatile("cp.async.wait_group 1;"); }
        else       { asm volatile("cp.async.wait_group 0;"); }
        __syncthreads();   // also orders last iter's reads of buf^1 before restage

        if (c < 5) {
            const float* src = xc + (c + 1) * 32;
            float* dst = bufs[buf ^ 1];
            for (int f = tid; f < 2048; f += 256) {
                int r = f >> 3, c4 = f & 7;
                CP_ASYNC16(smaddr(dst + r * XST + c4 * 4), src + r * 192 + c4 * 4);
            }
            CP_COMMIT();
        }

        const float* xs = bufs[buf] + (w * 32) * XST;
#pragma unroll
        for (int ks2 = 0; ks2 < 2; ks2++) {
            const int kb = ks2 * 16 + 2 * tg;
            unsigned a0[4], a1[4];
            {
                float2 v;
                v = *(const float2*)(xs + gq * XST + kb);           a0[0] = packh2(v.x, v.y);
                v = *(const float2*)(xs + (gq + 8) * XST + kb);     a0[1] = packh2(v.x, v.y);
                v = *(const float2*)(xs + gq * XST + kb + 8);       a0[2] = packh2(v.x, v.y);
                v = *(const float2*)(xs + (gq + 8) * XST + kb + 8); a0[3] = packh2(v.x, v.y);
                v = *(const float2*)(xs + (gq + 16) * XST + kb);        a1[0] = packh2(v.x, v.y);
                v = *(const float2*)(xs + (gq + 24) * XST + kb);        a1[1] = packh2(v.x, v.y);
                v = *(const float2*)(xs + (gq + 16) * XST + kb + 8);    a1[2] = packh2(v.x, v.y);
                v = *(const float2*)(xs + (gq + 24) * XST + kb + 8);    a1[3] = packh2(v.x, v.y);
            }
            const unsigned* wb = W_sh + (c * 16 + ks2 * 8 + tg) * WST + gq;
#pragma unroll
            for (int nt = 0; nt < 8; nt++) {
                unsigned b0 = wb[nt * 8];
                unsigned b1 = wb[4 * WST + nt * 8];
                mma_f16(acc[0][nt], a0, b0, b1);
                mma_f16(acc[1][nt], a1, b0, b1);
            }
        }
        buf ^= 1;
    }

    if (sel == 0) {
        const float scale = rsqrtf(192.0f);
        unsigned* qo = g_q + ((size_t)b * 256 + w * 32) * 32;
#pragma unroll
        for (int r = 0; r < 2; r++) {
            int r0 = r * 16 + gq;
#pragma unroll
            for (int nt = 0; nt < 8; nt++) {
                int wi = nt * 4 + tg;
                qo[r0 * 32 + wi] = packh2(acc[r][nt][0] * scale, acc[r][nt][1] * scale);
                qo[(r0 + 8) * 32 + wi] = packh2(acc[r][nt][2] * scale, acc[r][nt][3] * scale);
            }
        }
    } else if (sel == 1) {
        unsigned* ko = g_k + ((size_t)b * 256 + w * 32) * 32;
#pragma unroll
        for (int r = 0; r < 2; r++) {
            int r0 = r * 16 + gq;
#pragma unroll
            for (int nt = 0; nt < 8; nt++) {
                int wi = kperm(nt * 4 + tg);   // pair-permuted word
                ko[r0 * 32 + wi] = packh2(acc[r][nt][0], acc[r][nt][1]);
                ko[(r0 + 8) * 32 + wi] = packh2(acc[r][nt][2], acc[r][nt][3]);
            }
        }
    } else {
        // v -> [h][t] half with tile-local pair permutation on the t-pair index.
        unsigned* vo = g_vT + (size_t)b * 8192;
        const bool even = ((gq & 1) == 0);
#pragma unroll
        for (int r = 0; r < 2; r++) {
            int t0 = w * 32 + r * 16 + gq;
#pragma unroll
            for (int nt = 0; nt < 8; nt++) {
                int c = nt * 8 + 2 * tg;
                float a0 = acc[r][nt][0], a1 = acc[r][nt][1];
                float a2 = acc[r][nt][2], a3 = acc[r][nt][3];
                float p0 = __shfl_xor_sync(0xffffffffu, a0, 4);
                float p1 = __shfl_xor_sync(0xffffffffu, a1, 4);
                float p2 = __shfl_xor_sync(0xffffffffu, a2, 4);
                float p3 = __shfl_xor_sync(0xffffffffu, a3, 4);
                if (even) {
                    int g0 = vperm(t0 >> 1);
                    int g1 = vperm((t0 + 8) >> 1);
                    vo[c * 128 + g0]       = packh2(a0, p0);
                    vo[(c + 1) * 128 + g0] = packh2(a1, p1);
                    vo[c * 128 + g1]       = packh2(a2, p2);
                    vo[(c + 1) * 128 + g1] = packh2(a3, p3);
                }
            }
        }
    }
}

// ---------------------------------------------------------------------------
// Kernel 2 + 3: positional projections and bias (tiny, fp32 exact)
// ---------------------------------------------------------------------------
__global__ __launch_bounds__(256) void pos_kernel(const float* __restrict__ pe,
                                                  const float* __restrict__ Wk,
                                                  const float* __restrict__ Wq) {
    int idx = blockIdx.x * 256 + threadIdx.x;
    int t = idx >> 7;
    int j = idx & 127;
    const float* __restrict__ W = (j < 64) ? Wk : Wq;
    int col = j & 63;
    float s = 0.0f;
#pragma unroll 4
    for (int c = 0; c < 192; c++) s = fmaf(pe[t * 192 + c], W[c * 64 + col], s);
    g_pos[idx] = s;
}

__global__ __launch_bounds__(256) void bias_kernel() {
    int i = blockIdx.x;
    int j = threadIdx.x;
    float s = 0.0f;
#pragma unroll 4
    for (int h = 0; h < 64; h++)
        s = fmaf(g_pos[i * 128 + h], g_pos[j * 128 + 64 + h], s);
    g_bias[i * 256 + j] = s;
}

// ---------------------------------------------------------------------------
// Kernel 4: flash-block attention (round-14 base). K/V fragment pairs are
// pre-permuted in global so each mma B-pair is one LDS.64. Strides 40
// (64-bit phases: 8gq+2tg mod 32 all-distinct). smem 30KB, 2 CTAs/SM.
// ---------------------------------------------------------------------------
#define KSW 40
#define VSW 40
__global__ __launch_bounds__(256, 2) void attn_f16_kernel(float* __restrict__ out) {
    extern __shared__ unsigned smw[];
    unsigned* kbuf[2] = { smw, smw + 1280 };          // 32*40 words each
    unsigned* vbuf[2] = { smw + 2560, smw + 5120 };   // 64*40 words each

    const int qb = blockIdx.x;
    const int b  = blockIdx.y;
    const int tid = threadIdx.x, w = tid >> 5, lane = tid & 31;
    const int gq = lane >> 2, tg = lane & 3;
    const int nj = (qb + 1) * 4;

    const unsigned* __restrict__ kg = g_k + (size_t)b * 8192;    // [t][32w perm]
    const unsigned* __restrict__ vg = g_vT + (size_t)b * 8192;   // [h][128w perm]

    const int rowg = qb * 128 + gq * 8 + w;
    const int row2 = rowg + 64;

    // Q fragments (packed half2): 16 x 32-bit loads
    unsigned qa[4][4];
    {
        const unsigned* __restrict__ qh = g_q + ((size_t)b * 256 + qb * 128) * 32;
        const int r0 = gq * 8 + w, r1 = r0 + 64;
#pragma unroll
        for (int kk = 0; kk < 4; kk++) {
            qa[kk][0] = qh[r0 * 32 + kk * 8 + tg];
            qa[kk][1] = qh[r1 * 32 + kk * 8 + tg];
            qa[kk][2] = qh[r0 * 32 + kk * 8 + tg + 4];
            qa[kk][3] = qh[r1 * 32 + kk * 8 + tg + 4];
        }
    }

    float o[8][4];
#pragma unroll
    for (int n = 0; n < 8; n++)
#pragma unroll
        for (int i = 0; i < 4; i++) o[n][i] = 0.0f;
    float m0 = -1e30f, m1 = -1e30f, l0 = 0.0f, l1 = 0.0f;

    // Prologue: stage tile 0. K: 32 rows x 8 chunks; V: 64 rows x 4 chunks.
    for (int f = tid; f < 512; f += 256) {
        if (f < 256) {
            int r = f >> 3, c8 = f & 7;
            CP_ASYNC16(smaddr(kbuf[0] + r * KSW + c8 * 4), kg + r * 32 + c8 * 4);
        } else {
            int g = f - 256;
            int h = g >> 2, c4 = g & 3;
            CP_ASYNC16(smaddr(vbuf[0] + h * VSW + c4 * 4), vg + h * 128 + c4 * 4);
        }
    }
    CP_COMMIT();

    int buf = 0;
    for (int jt = 0; jt < nj; jt++) {
        const int j0 = jt * 32;
        asm volatile("cp.async.wait_group 0;");
        __syncthreads();

        if (jt + 1 < nj) {
            const int jn = j0 + 32;
            unsigned* kn = kbuf[buf ^ 1];
            unsigned* vn = vbuf[buf ^ 1];
            for (int f = tid; f < 512; f += 256) {
                if (f < 256) {
                    int r = f >> 3, c8 = f & 7;
                    CP_ASYNC16(smaddr(kn + r * KSW + c8 * 4),
                               kg + (jn + r) * 32 + c8 * 4);
                } else {
                    int g = f - 256;
                    int h = g >> 2, c4 = g & 3;
                    CP_ASYNC16(smaddr(vn + h * VSW + c4 * 4),
                               vg + h * 128 + (jn >> 1) + c4 * 4);
                }
            }
            CP_COMMIT();
        }

        const unsigned* kb = kbuf[buf];
        const unsigned* vb = vbuf[buf];

        // Hoisted bias loads (independent of the mma chain below)
        float2 bv0[4], bv1[4];
        {
            const float* __restrict__ br0 = g_bias + (size_t)rowg * 256 + j0;
            const float* __restrict__ br1 = g_bias + (size_t)row2 * 256 + j0;
#pragma unroll
            for (int nt = 0; nt < 4; nt++) {
                int c = nt * 8 + 2 * tg;
                bv0[nt] = *(const float2*)(br0 + c);
                bv1[nt] = *(const float2*)(br1 + c);
            }
        }

        // S = Q K^T  (q pre-scaled): 16 mmas, B pair = one LDS.64
        float s[4][4];
#pragma unroll
        for (int n = 0; n < 4; n++)
#pragma unroll
            for (int i = 0; i < 4; i++) s[n][i] = 0.0f;
#pragma unroll
        for (int kk = 0; kk < 4; kk++) {
#pragma unroll
            for (int nt = 0; nt < 4; nt++) {
                const uint2 kv = *(const uint2*)(kb + (nt * 8 + gq) * KSW
                                                 + kk * 8 + 2 * tg);
                mma_f16(s[nt], qa[kk], kv.x, kv.y);
            }
        }

        // + bias, causal mask
#pragma unroll
        for (int nt = 0; nt < 4; nt++) {
            int c = nt * 8 + 2 * tg;
            int col = j0 + c;
            s[nt][0] = (col     <= rowg) ? (s[nt][0] + bv0[nt].x) : -1e30f;
            s[nt][1] = (col + 1 <= rowg) ? (s[nt][1] + bv0[nt].y) : -1e30f;
            s[nt][2] = (col     <= row2) ? (s[nt][2] + bv1[nt].x) : -1e30f;
            s[nt][3] = (col + 1 <= row2) ? (s[nt][3] + bv1[nt].y) : -1e30f;
        }

        // online softmax
        float mx0 = -1e30f, mx1 = -1e30f;
#pragma unroll
        for (int nt = 0; nt < 4; nt++) {
            mx0 = fmaxf(mx0, fmaxf(s[nt][0], s[nt][1]));
            mx1 = fmaxf(mx1, fmaxf(s[nt][2], s[nt][3]));
        }
        mx0 = fmaxf(mx0, __shfl_xor_sync(0xffffffffu, mx0, 1));
        mx0 = fmaxf(mx0, __shfl_xor_sync(0xffffffffu, mx0, 2));
        mx1 = fmaxf(mx1, __shfl_xor_sync(0xffffffffu, mx1, 1));
        mx1 = fmaxf(mx1, __shfl_xor_sync(0xffffffffu, mx1, 2));
        float mn0 = fmaxf(m0, mx0), mn1 = fmaxf(m1, mx1);
        float al0 = __expf(m0 - mn0), al1 = __expf(m1 - mn1);
        m0 = mn0; m1 = mn1;

        float sum0 = 0.0f, sum1 = 0.0f;
        float e[4][4];
#pragma unroll
        for (int nt = 0; nt < 4; nt++) {
            e[nt][0] = __expf(s[nt][0] - mn0);
            e[nt][1] = __expf(s[nt][1] - mn0);
            e[nt][2] = __expf(s[nt][2] - mn1);
            e[nt][3] = __expf(s[nt][3] - mn1);
            sum0 += e[nt][0] + e[nt][1];
            sum1 += e[nt][2] + e[nt][3];
        }
        sum0 += __shfl_xor_sync(0xffffffffu, sum0, 1);
        sum0 += __shfl_xor_sync(0xffffffffu, sum0, 2);
        sum1 += __shfl_xor_sync(0xffffffffu, sum1, 1);
        sum1 += __shfl_xor_sync(0xffffffffu, sum1, 2);
        l0 = l0 * al0 + sum0;
        l1 = l1 * al1 + sum1;

#pragma unroll
        for (int nt = 0; nt < 8; nt++) {
            o[nt][0] *= al0; o[nt][1] *= al0;
            o[nt][2] *= al1; o[nt][3] *= al1;
        }

        // O += P V : P A-frags packed directly from e (C-frag == A-frag);
        // V B pair = one LDS.64
#pragma unroll
        for (int ks = 0; ks < 2; ks++) {
            unsigned pa[4];
            pa[0] = packh2(e[2 * ks][0],     e[2 * ks][1]);
            pa[1] = packh2(e[2 * ks][2],     e[2 * ks][3]);
            pa[2] = packh2(e[2 * ks + 1][0], e[2 * ks + 1][1]);
            pa[3] = packh2(e[2 * ks + 1][2], e[2 * ks + 1][3]);
#pragma unroll
            for (int nt = 0; nt < 8; nt++) {
                const uint2 vv = *(const uint2*)(vb + (nt * 8 + gq) * VSW
                                                 + ks * 8 + 2 * tg);
                mma_f16(o[nt], pa, vv.x, vv.y);
            }
        }
        // no bottom __syncthreads — next iteration's top barrier orders restaging
        buf ^= 1;
    }

    float inv0 = 1.0f / l0, inv1 = 1.0f / l1;
    float* ob = out + ((size_t)b * 256) * 64;
#pragma unroll
    for (int nt = 0; nt < 8; nt++) {
        int c = nt * 8 + 2 * tg;
        *(float2*)(ob + (size_t)rowg * 64 + c) =
            make_float2(o[nt][0] * inv0, o[nt][1] * inv0);
        *(float2*)(ob + (size_t)row2 * 64 + c) =
            make_float2(o[nt][2] * inv1, o[nt][3] * inv1);
    }
}

// ---------------------------------------------------------------------------
extern "C" void kernel_launch(void* const* d_in, const int* in_sizes, int n_in,
                              void* d_out, int out_size) {
    const float* x  = (const float*)d_in[0];
    const float* Wk = (const float*)d_in[1];
    const float* Wq = (const float*)d_in[2];
    const float* Wv = (const float*)d_in[3];
    const float* pe = (const float*)d_in[4];
    float* out = (float*)d_out;
    (void)in_sizes; (void)n_in; (void)out_size;

    static bool attr_set = false;
    if (!attr_set) {
        cudaFuncSetAttribute(qkv_f16_kernel,
                             cudaFuncAttributeMaxDynamicSharedMemorySize, 109568);
        cudaFuncSetAttribute(attn_f16_kernel,
                             cudaFuncAttributeMaxDynamicSharedMemorySize, 30720);
        attr_set = true;
    }

    qkv_f16_kernel<<<dim3(3, 512), 256, 109568>>>(x, Wq, Wk, Wv);
    pos_kernel<<<128, 256>>>(pe, Wk, Wq);
    bias_kernel<<<256, 256>>>();
    attn_f16_kernel<<<dim3(2, 512), 256, 30720>>>(out);
}